// round 5
// baseline (speedup 1.0000x reference)
#include <cuda_runtime.h>
#include <cmath>

#define TT   120
#define DD   64
#define DHH  32
#define NHH  2
#define DFF_ 128
#define DOUT_ 31
#define SCALE_ 0.17677669529663687f   // 1/sqrt(32)

// scratch (device globals: no allocation allowed)
__device__ float g_cross[TT * DD];
__device__ float g_h1[TT * DD];

// ---------------------------------------------------------------------------
// LayerNorm over 64 smem values, in place. All threads of block must call.
// ---------------------------------------------------------------------------
__device__ __forceinline__ void ln64_inplace(float* x, const float* g,
                                             const float* b, int tid,
                                             float* red) {
    __syncthreads();
    if (tid < 32) {
        float a = x[tid], c = x[tid + 32];
        float s = a + c, q = a * a + c * c;
#pragma unroll
        for (int o = 16; o; o >>= 1) {
            s += __shfl_xor_sync(0xffffffffu, s, o);
            q += __shfl_xor_sync(0xffffffffu, q, o);
        }
        if (tid == 0) {
            float m = s * (1.f / 64.f);
            red[0] = m;
            red[1] = rsqrtf(q * (1.f / 64.f) - m * m + 1e-5f);
        }
    }
    __syncthreads();
    if (tid < 64) x[tid] = (x[tid] - red[0]) * red[1] * g[tid] + b[tid];
    __syncthreads();
}

// ---------------------------------------------------------------------------
// Kernel 1: per-row  mem_t = audio[t] @ W_audio^T + b_audio  (64 x 1024 dot)
//           cross_t = (mem_t @ Wv2^T + bv2) @ Wo2^T + bo2
// 120 blocks x 256 threads (4 threads per output, shuffle reduce)
// ---------------------------------------------------------------------------
__global__ void k1_mem_cross(const float* __restrict__ audio,
                             const float* __restrict__ W_audio,
                             const float* __restrict__ b_audio,
                             const float* __restrict__ Wv2,
                             const float* __restrict__ bv2,
                             const float* __restrict__ Wo2,
                             const float* __restrict__ bo2) {
    int t = blockIdx.x;
    int tid = threadIdx.x;
    int o = tid >> 2, sgi = tid & 3;
    __shared__ float memv[64], tmp[64];

    const float4* a = (const float4*)(audio + t * 1024);
    const float4* w = (const float4*)(W_audio + o * 1024);
    float acc = 0.f;
    int base = sgi * 64;
#pragma unroll 8
    for (int j = 0; j < 64; j++) {
        float4 av = a[base + j], wv = w[base + j];
        acc += av.x * wv.x + av.y * wv.y + av.z * wv.z + av.w * wv.w;
    }
    acc += __shfl_xor_sync(0xffffffffu, acc, 1);
    acc += __shfl_xor_sync(0xffffffffu, acc, 2);
    if (sgi == 0) memv[o] = acc + b_audio[o];
    __syncthreads();

    float a2 = 0.f;
#pragma unroll
    for (int j = sgi; j < 64; j += 4) a2 += memv[j] * Wv2[o * 64 + j];
    a2 += __shfl_xor_sync(0xffffffffu, a2, 1);
    a2 += __shfl_xor_sync(0xffffffffu, a2, 2);
    if (sgi == 0) tmp[o] = a2 + bv2[o];
    __syncthreads();

    float a3 = 0.f;
#pragma unroll
    for (int j = sgi; j < 64; j += 4) a3 += tmp[j] * Wo2[o * 64 + j];
    a3 += __shfl_xor_sync(0xffffffffu, a3, 1);
    a3 += __shfl_xor_sync(0xffffffffu, a3, 2);
    if (sgi == 0) g_cross[t * 64 + o] = a3 + bo2[o];
}

// ---------------------------------------------------------------------------
// Kernel 2: sequential 120-step recurrence. ONE block, 256 threads.
// All weights (transposed, padded rows to kill bank conflicts) + K/V caches
// live in shared memory. h1[t] is saved to global for kernel 3.
// ---------------------------------------------------------------------------
struct S2 {
    float WqT[64 * 65];
    float WkT[64 * 65];
    float WvT[64 * 65];
    float WoT[64 * 65];
    float W1T[64 * 129];   // [in j<64][out i<128]
    float W2T[128 * 65];   // [in j<128][out i<64]
    float WrT[64 * 33];    // [in j<64][out i<31]
    float WmT[31 * 65];    // [in j<31][out i<64]
    float kcT[64 * 128];   // [dim][time]  (time padded to 128)
    float vc[120 * 65];    // [time][dim]  (dim padded to 65)
    float pe[10 * 64];
    float bq[64], bk[64], bv[64], bo[64];
    float c1[128], c2[64];
    float br[32], bm[64];
    float g1[64], be1[64], g2[64], be2[64], g3[64], be3[64];
    float cl[64], style[64];
    float cur[64], xq[64], q[64];
    float sc[2 * 128];
    float sa[64], h1[64], h2[64], u[128], h3[64], r[32];
    float red[2];
    float inv2[2];
};

__global__ void __launch_bounds__(256, 1)
k2_seq(const float* __restrict__ Wq, const float* __restrict__ bq,
       const float* __restrict__ Wk, const float* __restrict__ bk,
       const float* __restrict__ Wv, const float* __restrict__ bv,
       const float* __restrict__ Wo, const float* __restrict__ bo,
       const float* __restrict__ g1, const float* __restrict__ be1,
       const float* __restrict__ g2, const float* __restrict__ be2,
       const float* __restrict__ g3, const float* __restrict__ be3,
       const float* __restrict__ W1, const float* __restrict__ c1,
       const float* __restrict__ W2, const float* __restrict__ c2,
       const float* __restrict__ Wr, const float* __restrict__ br,
       const float* __restrict__ Wm, const float* __restrict__ bm,
       const float* __restrict__ obj_W) {
    extern __shared__ char raw[];
    S2& s = *reinterpret_cast<S2*>(raw);
    int tid = threadIdx.x;

    // ---- load weights (transposed) ----
    for (int idx = tid; idx < 4096; idx += 256) {
        int i = idx >> 6, j = idx & 63;
        s.WqT[j * 65 + i] = Wq[idx];
        s.WkT[j * 65 + i] = Wk[idx];
        s.WvT[j * 65 + i] = Wv[idx];
        s.WoT[j * 65 + i] = Wo[idx];
    }
    for (int idx = tid; idx < 8192; idx += 256) {       // W1 is (128,64)
        int i = idx >> 6, j = idx & 63;
        s.W1T[j * 129 + i] = W1[idx];
    }
    for (int idx = tid; idx < 8192; idx += 256) {       // W2 is (64,128)
        int i = idx >> 7, j = idx & 127;
        s.W2T[j * 65 + i] = W2[idx];
    }
    for (int idx = tid; idx < 31 * 64; idx += 256) {    // Wr is (31,64)
        int i = idx >> 6, j = idx & 63;
        s.WrT[j * 33 + i] = Wr[idx];
    }
    for (int idx = tid; idx < 64 * 31; idx += 256) {    // Wm is (64,31)
        int i = idx / 31, j = idx % 31;
        s.WmT[j * 65 + i] = Wm[idx];
    }
    if (tid < 64) {
        s.bq[tid] = bq[tid]; s.bk[tid] = bk[tid];
        s.bv[tid] = bv[tid]; s.bo[tid] = bo[tid];
        s.c2[tid] = c2[tid]; s.bm[tid] = bm[tid];
        s.g1[tid] = g1[tid]; s.be1[tid] = be1[tid];
        s.g2[tid] = g2[tid]; s.be2[tid] = be2[tid];
        s.g3[tid] = g3[tid]; s.be3[tid] = be3[tid];
        s.cl[tid] = g_cross[(TT - 1) * 64 + tid];
        float st = obj_W[tid * 5];          // obj_W[:,0], shape (64,5)
        s.style[tid] = st;
        s.cur[tid] = st;                    // emb[0] = style
    }
    if (tid < 128) s.c1[tid] = c1[tid];
    if (tid < 31) s.br[tid] = br[tid];
    // positional encoding (period 10, interleaved sin/cos)
    for (int idx = tid; idx < 640; idx += 256) {
        int p = idx >> 6, d = idx & 63;
        int i = d >> 1;
        float div = expf(-(float)(2 * i) * (9.210340371976184f / 64.f));
        float arg = (float)p * div;
        s.pe[idx] = (d & 1) ? cosf(arg) : sinf(arg);
    }
    __syncthreads();

    const float slopes[2] = {0.0625f, 0.00390625f};

    for (int t = 0; t < TT; t++) {
        // xq = emb[t] + pe[t % 10]
        if (tid < 64) s.xq[tid] = s.cur[tid] + s.pe[(t % 10) * 64 + tid];
        __syncthreads();

        // q / k_t / v_t  (192 outputs, one thread each, 64-term dot)
        if (tid < 192) {
            int which = tid >> 6, i = tid & 63;
            const float* WT = (which == 0) ? s.WqT : (which == 1) ? s.WkT : s.WvT;
            float acc = 0.f;
#pragma unroll
            for (int j = 0; j < 64; j++) acc += s.xq[j] * WT[j * 65 + i];
            if (which == 0)      s.q[i] = acc + s.bq[i];
            else if (which == 1) s.kcT[i * 128 + t] = acc + s.bk[i];
            else                 s.vc[t * 65 + i] = acc + s.bv[i];
        }
        __syncthreads();

        // attention scores: s[h][j] = (q_h . k_j,h)*SCALE - slope_h*((t-j)/10)
        int n = t + 1;
        if (tid < 2 * n) {
            int h = (tid >= n) ? 1 : 0;
            int j = tid - h * n;
            float acc = 0.f;
#pragma unroll
            for (int d = 0; d < 32; d++)
                acc += s.q[h * 32 + d] * s.kcT[(h * 32 + d) * 128 + j];
            s.sc[h * 128 + j] = acc * SCALE_ - slopes[h] * (float)((t - j) / 10);
        }
        __syncthreads();

        // softmax per head: warp 0 -> head 0, warp 1 -> head 1
        {
            int w = tid >> 5, lane = tid & 31;
            if (w < 2) {
                float m = -1e30f;
                for (int j = lane; j < n; j += 32) m = fmaxf(m, s.sc[w * 128 + j]);
#pragma unroll
                for (int o = 16; o; o >>= 1) m = fmaxf(m, __shfl_xor_sync(0xffffffffu, m, o));
                float ssum = 0.f;
                for (int j = lane; j < n; j += 32) {
                    float e = expf(s.sc[w * 128 + j] - m);
                    s.sc[w * 128 + j] = e;
                    ssum += e;
                }
#pragma unroll
                for (int o = 16; o; o >>= 1) ssum += __shfl_xor_sync(0xffffffffu, ssum, o);
                if (lane == 0) s.inv2[w] = 1.f / ssum;
            }
        }
        __syncthreads();

        // sa[o] = sum_j p[h][j] * v[j][o]   (split-4 over j within warp)
        {
            int o = tid >> 2, sgi = tid & 3;
            int h = o >> 5;
            float acc = 0.f;
            for (int j = sgi; j < n; j += 4) acc += s.sc[h * 128 + j] * s.vc[j * 65 + o];
            acc += __shfl_xor_sync(0xffffffffu, acc, 1);
            acc += __shfl_xor_sync(0xffffffffu, acc, 2);
            if (sgi == 0) s.sa[o] = acc * s.inv2[h];
        }
        __syncthreads();

        // out proj + residual  ->  h1 pre-LN
        {
            int o = tid >> 2, sgi = tid & 3;
            float acc = 0.f;
#pragma unroll
            for (int j = sgi; j < 64; j += 4) acc += s.sa[j] * s.WoT[j * 65 + o];
            acc += __shfl_xor_sync(0xffffffffu, acc, 1);
            acc += __shfl_xor_sync(0xffffffffu, acc, 2);
            if (sgi == 0) s.h1[o] = s.xq[o] + acc + s.bo[o];
        }
        ln64_inplace(s.h1, s.g1, s.be1, tid, s.red);

        // persist h1 (kernel 3 computes the real output using cross[t])
        if (tid < 64) g_h1[t * 64 + tid] = s.h1[tid];
        if (t == TT - 1) break;   // last row: only h1 is needed

        // h2 = LN(h1 + cross_last)
        if (tid < 64) s.h2[tid] = s.h1[tid] + s.cl[tid];
        ln64_inplace(s.h2, s.g2, s.be2, tid, s.red);

        // FFN up:  u = relu(h2 @ W1^T + c1)  (128 outputs, split-2)
        {
            int o = tid >> 1, sgi = tid & 1;
            float acc = 0.f;
#pragma unroll
            for (int j = sgi; j < 64; j += 2) acc += s.h2[j] * s.W1T[j * 129 + o];
            acc += __shfl_xor_sync(0xffffffffu, acc, 1);
            if (sgi == 0) s.u[o] = fmaxf(acc + s.c1[o], 0.f);
        }
        __syncthreads();

        // FFN down + residual -> h3 pre-LN  (64 outputs, split-4 over 128)
        {
            int o = tid >> 2, sgi = tid & 3;
            float acc = 0.f;
#pragma unroll
            for (int j = sgi; j < 128; j += 4) acc += s.u[j] * s.W2T[j * 65 + o];
            acc += __shfl_xor_sync(0xffffffffu, acc, 1);
            acc += __shfl_xor_sync(0xffffffffu, acc, 2);
            if (sgi == 0) s.h3[o] = s.h2[o] + acc + s.c2[o];
        }
        ln64_inplace(s.h3, s.g3, s.be3, tid, s.red);

        // r = h3 @ Wr^T + br  (31 outputs, split-4)
        {
            int o = tid >> 2, sgi = tid & 3;
            if (o < 32) {
                float acc = 0.f;
#pragma unroll
                for (int j = sgi; j < 64; j += 4) acc += s.h3[j] * s.WrT[j * 33 + o];
                acc += __shfl_xor_sync(0xffffffffu, acc, 1);
                acc += __shfl_xor_sync(0xffffffffu, acc, 2);
                if (sgi == 0 && o < 31) s.r[o] = acc + s.br[o];
            }
        }
        __syncthreads();

        // emb[t+1] = r @ Wm^T + bm + style  (64 outputs, split-4 over 31)
        {
            int o = tid >> 2, sgi = tid & 3;
            float acc = 0.f;
            for (int j = sgi; j < 31; j += 4) acc += s.r[j] * s.WmT[j * 65 + o];
            acc += __shfl_xor_sync(0xffffffffu, acc, 1);
            acc += __shfl_xor_sync(0xffffffffu, acc, 2);
            if (sgi == 0) s.cur[o] = acc + s.bm[o] + s.style[o];
        }
        __syncthreads();
    }
}

// ---------------------------------------------------------------------------
// Kernel 3: per-row output tail (uses per-row cross[t], unlike the loop)
//   h2 = LN(h1[t] + cross[t]); h3 = LN(h2 + FFN(h2)); out = h3 @ Wr^T + br
// 120 blocks x 128 threads
// ---------------------------------------------------------------------------
__global__ void k3_out(const float* __restrict__ W1, const float* __restrict__ c1,
                       const float* __restrict__ W2, const float* __restrict__ c2,
                       const float* __restrict__ Wr, const float* __restrict__ br,
                       const float* __restrict__ g2, const float* __restrict__ be2,
                       const float* __restrict__ g3, const float* __restrict__ be3,
                       float* __restrict__ out) {
    int t = blockIdx.x, tid = threadIdx.x;
    __shared__ float h2[64], u[128], h3[64], red[2];

    if (tid < 64) h2[tid] = g_h1[t * 64 + tid] + g_cross[t * 64 + tid];
    ln64_inplace(h2, g2, be2, tid, red);

    float acc = c1[tid];
#pragma unroll 8
    for (int j = 0; j < 64; j++) acc += h2[j] * W1[tid * 64 + j];
    u[tid] = fmaxf(acc, 0.f);
    __syncthreads();

    if (tid < 64) {
        float a2 = c2[tid];
#pragma unroll 8
        for (int j = 0; j < 128; j++) a2 += u[j] * W2[tid * 128 + j];
        h3[tid] = h2[tid] + a2;
    }
    ln64_inplace(h3, g3, be3, tid, red);

    if (tid < 31) {
        float a3 = br[tid];
#pragma unroll 8
        for (int j = 0; j < 64; j++) a3 += h3[j] * Wr[tid * 64 + j];
        out[t * 31 + tid] = a3;
    }
}

// ---------------------------------------------------------------------------
extern "C" void kernel_launch(void* const* d_in, const int* in_sizes, int n_in,
                              void* d_out, int out_size) {
    const float* audio   = (const float*)d_in[0];
    const float* W_audio = (const float*)d_in[1];
    const float* b_audio = (const float*)d_in[2];
    const float* obj_W   = (const float*)d_in[3];
    const float* Wq = (const float*)d_in[4];  const float* bq = (const float*)d_in[5];
    const float* Wk = (const float*)d_in[6];  const float* bk = (const float*)d_in[7];
    const float* Wv = (const float*)d_in[8];  const float* bv = (const float*)d_in[9];
    const float* Wo = (const float*)d_in[10]; const float* bo = (const float*)d_in[11];
    const float* Wv2 = (const float*)d_in[12]; const float* bv2 = (const float*)d_in[13];
    const float* Wo2 = (const float*)d_in[14]; const float* bo2 = (const float*)d_in[15];
    const float* g1 = (const float*)d_in[16]; const float* be1 = (const float*)d_in[17];
    const float* g2 = (const float*)d_in[18]; const float* be2 = (const float*)d_in[19];
    const float* g3 = (const float*)d_in[20]; const float* be3 = (const float*)d_in[21];
    const float* W1 = (const float*)d_in[22]; const float* c1 = (const float*)d_in[23];
    const float* W2 = (const float*)d_in[24]; const float* c2 = (const float*)d_in[25];
    const float* Wr = (const float*)d_in[26]; const float* br = (const float*)d_in[27];
    const float* Wm = (const float*)d_in[28]; const float* bm = (const float*)d_in[29];
    float* out = (float*)d_out;

    cudaFuncSetAttribute(k2_seq, cudaFuncAttributeMaxDynamicSharedMemorySize,
                         (int)sizeof(S2));

    k1_mem_cross<<<TT, 256>>>(audio, W_audio, b_audio, Wv2, bv2, Wo2, bo2);
    k2_seq<<<1, 256, sizeof(S2)>>>(Wq, bq, Wk, bk, Wv, bv, Wo, bo,
                                   g1, be1, g2, be2, g3, be3,
                                   W1, c1, W2, c2, Wr, br, Wm, bm, obj_W);
    k3_out<<<TT, 128>>>(W1, c1, W2, c2, Wr, br, g2, be2, g3, be3, out);
}

// round 6
// speedup vs baseline: 1.0014x; 1.0014x over previous
#include <cuda_runtime.h>
#include <cmath>

#define TT   120
#define DD   64
#define DHH  32
#define NHH  2
#define DFF_ 128
#define DOUT_ 31
#define SCALE_ 0.17677669529663687f   // 1/sqrt(32)

// scratch (device globals: no allocation allowed)
__device__ float g_cross[TT * DD];
__device__ float g_h1[TT * DD];

// ---------------------------------------------------------------------------
// LayerNorm over 64 smem values, in place. All threads of block must call.
// ---------------------------------------------------------------------------
__device__ __forceinline__ void ln64_inplace(float* x, const float* g,
                                             const float* b, int tid,
                                             float* red) {
    __syncthreads();
    if (tid < 32) {
        float a = x[tid], c = x[tid + 32];
        float s = a + c, q = a * a + c * c;
#pragma unroll
        for (int o = 16; o; o >>= 1) {
            s += __shfl_xor_sync(0xffffffffu, s, o);
            q += __shfl_xor_sync(0xffffffffu, q, o);
        }
        if (tid == 0) {
            float m = s * (1.f / 64.f);
            red[0] = m;
            red[1] = rsqrtf(q * (1.f / 64.f) - m * m + 1e-5f);
        }
    }
    __syncthreads();
    if (tid < 64) x[tid] = (x[tid] - red[0]) * red[1] * g[tid] + b[tid];
    __syncthreads();
}

// ---------------------------------------------------------------------------
// Kernel 1: per-row  mem_t = audio[t] @ W_audio^T + b_audio  (64 x 1024 dot)
//           cross_t = (mem_t @ Wv2^T + bv2) @ Wo2^T + bo2
// 120 blocks x 256 threads (4 threads per output, shuffle reduce)
// ---------------------------------------------------------------------------
__global__ void k1_mem_cross(const float* __restrict__ audio,
                             const float* __restrict__ W_audio,
                             const float* __restrict__ b_audio,
                             const float* __restrict__ Wv2,
                             const float* __restrict__ bv2,
                             const float* __restrict__ Wo2,
                             const float* __restrict__ bo2) {
    int t = blockIdx.x;
    int tid = threadIdx.x;
    int o = tid >> 2, sgi = tid & 3;
    __shared__ float memv[64], tmp[64];

    const float4* a = (const float4*)(audio + t * 1024);
    const float4* w = (const float4*)(W_audio + o * 1024);
    float acc = 0.f;
    int base = sgi * 64;
#pragma unroll 8
    for (int j = 0; j < 64; j++) {
        float4 av = a[base + j], wv = w[base + j];
        acc += av.x * wv.x + av.y * wv.y + av.z * wv.z + av.w * wv.w;
    }
    acc += __shfl_xor_sync(0xffffffffu, acc, 1);
    acc += __shfl_xor_sync(0xffffffffu, acc, 2);
    if (sgi == 0) memv[o] = acc + b_audio[o];
    __syncthreads();

    float a2 = 0.f;
#pragma unroll
    for (int j = sgi; j < 64; j += 4) a2 += memv[j] * Wv2[o * 64 + j];
    a2 += __shfl_xor_sync(0xffffffffu, a2, 1);
    a2 += __shfl_xor_sync(0xffffffffu, a2, 2);
    if (sgi == 0) tmp[o] = a2 + bv2[o];
    __syncthreads();

    float a3 = 0.f;
#pragma unroll
    for (int j = sgi; j < 64; j += 4) a3 += tmp[j] * Wo2[o * 64 + j];
    a3 += __shfl_xor_sync(0xffffffffu, a3, 1);
    a3 += __shfl_xor_sync(0xffffffffu, a3, 2);
    if (sgi == 0) g_cross[t * 64 + o] = a3 + bo2[o];
}

// ---------------------------------------------------------------------------
// Kernel 2: sequential 120-step recurrence. ONE block, 256 threads.
// All weights (transposed, padded rows to kill bank conflicts) + K/V caches
// live in shared memory. h1[t] is saved to global for kernel 3.
// ---------------------------------------------------------------------------
struct S2 {
    float WqT[64 * 65];
    float WkT[64 * 65];
    float WvT[64 * 65];
    float WoT[64 * 65];
    float W1T[64 * 129];   // [in j<64][out i<128]
    float W2T[128 * 65];   // [in j<128][out i<64]
    float WrT[64 * 33];    // [in j<64][out i<31]
    float WmT[31 * 65];    // [in j<31][out i<64]
    float kcT[64 * 128];   // [dim][time]  (time padded to 128)
    float vc[120 * 65];    // [time][dim]  (dim padded to 65)
    float pe[10 * 64];
    float bq[64], bk[64], bv[64], bo[64];
    float c1[128], c2[64];
    float br[32], bm[64];
    float g1[64], be1[64], g2[64], be2[64], g3[64], be3[64];
    float cl[64], style[64];
    float cur[64], xq[64], q[64];
    float sc[2 * 128];
    float sa[64], h1[64], h2[64], u[128], h3[64], r[32];
    float red[2];
    float inv2[2];
};

__global__ void __launch_bounds__(256, 1)
k2_seq(const float* __restrict__ Wq, const float* __restrict__ bq,
       const float* __restrict__ Wk, const float* __restrict__ bk,
       const float* __restrict__ Wv, const float* __restrict__ bv,
       const float* __restrict__ Wo, const float* __restrict__ bo,
       const float* __restrict__ g1, const float* __restrict__ be1,
       const float* __restrict__ g2, const float* __restrict__ be2,
       const float* __restrict__ g3, const float* __restrict__ be3,
       const float* __restrict__ W1, const float* __restrict__ c1,
       const float* __restrict__ W2, const float* __restrict__ c2,
       const float* __restrict__ Wr, const float* __restrict__ br,
       const float* __restrict__ Wm, const float* __restrict__ bm,
       const float* __restrict__ obj_W) {
    extern __shared__ char raw[];
    S2& s = *reinterpret_cast<S2*>(raw);
    int tid = threadIdx.x;

    // ---- load weights (transposed) ----
    for (int idx = tid; idx < 4096; idx += 256) {
        int i = idx >> 6, j = idx & 63;
        s.WqT[j * 65 + i] = Wq[idx];
        s.WkT[j * 65 + i] = Wk[idx];
        s.WvT[j * 65 + i] = Wv[idx];
        s.WoT[j * 65 + i] = Wo[idx];
    }
    for (int idx = tid; idx < 8192; idx += 256) {       // W1 is (128,64)
        int i = idx >> 6, j = idx & 63;
        s.W1T[j * 129 + i] = W1[idx];
    }
    for (int idx = tid; idx < 8192; idx += 256) {       // W2 is (64,128)
        int i = idx >> 7, j = idx & 127;
        s.W2T[j * 65 + i] = W2[idx];
    }
    for (int idx = tid; idx < 31 * 64; idx += 256) {    // Wr is (31,64)
        int i = idx >> 6, j = idx & 63;
        s.WrT[j * 33 + i] = Wr[idx];
    }
    for (int idx = tid; idx < 64 * 31; idx += 256) {    // Wm is (64,31)
        int i = idx / 31, j = idx % 31;
        s.WmT[j * 65 + i] = Wm[idx];
    }
    if (tid < 64) {
        s.bq[tid] = bq[tid]; s.bk[tid] = bk[tid];
        s.bv[tid] = bv[tid]; s.bo[tid] = bo[tid];
        s.c2[tid] = c2[tid]; s.bm[tid] = bm[tid];
        s.g1[tid] = g1[tid]; s.be1[tid] = be1[tid];
        s.g2[tid] = g2[tid]; s.be2[tid] = be2[tid];
        s.g3[tid] = g3[tid]; s.be3[tid] = be3[tid];
        s.cl[tid] = g_cross[(TT - 1) * 64 + tid];
        float st = obj_W[tid * 5];          // obj_W[:,0], shape (64,5)
        s.style[tid] = st;
        s.cur[tid] = st;                    // emb[0] = style
    }
    if (tid < 128) s.c1[tid] = c1[tid];
    if (tid < 31) s.br[tid] = br[tid];
    // positional encoding (period 10, interleaved sin/cos)
    for (int idx = tid; idx < 640; idx += 256) {
        int p = idx >> 6, d = idx & 63;
        int i = d >> 1;
        float div = expf(-(float)(2 * i) * (9.210340371976184f / 64.f));
        float arg = (float)p * div;
        s.pe[idx] = (d & 1) ? cosf(arg) : sinf(arg);
    }
    __syncthreads();

    const float slopes[2] = {0.0625f, 0.00390625f};

    for (int t = 0; t < TT; t++) {
        // xq = emb[t] + pe[t % 10]
        if (tid < 64) s.xq[tid] = s.cur[tid] + s.pe[(t % 10) * 64 + tid];
        __syncthreads();

        // q / k_t / v_t  (192 outputs, one thread each, 64-term dot)
        if (tid < 192) {
            int which = tid >> 6, i = tid & 63;
            const float* WT = (which == 0) ? s.WqT : (which == 1) ? s.WkT : s.WvT;
            float acc = 0.f;
#pragma unroll
            for (int j = 0; j < 64; j++) acc += s.xq[j] * WT[j * 65 + i];
            if (which == 0)      s.q[i] = acc + s.bq[i];
            else if (which == 1) s.kcT[i * 128 + t] = acc + s.bk[i];
            else                 s.vc[t * 65 + i] = acc + s.bv[i];
        }
        __syncthreads();

        // attention scores: s[h][j] = (q_h . k_j,h)*SCALE - slope_h*((t-j)/10)
        int n = t + 1;
        if (tid < 2 * n) {
            int h = (tid >= n) ? 1 : 0;
            int j = tid - h * n;
            float acc = 0.f;
#pragma unroll
            for (int d = 0; d < 32; d++)
                acc += s.q[h * 32 + d] * s.kcT[(h * 32 + d) * 128 + j];
            s.sc[h * 128 + j] = acc * SCALE_ - slopes[h] * (float)((t - j) / 10);
        }
        __syncthreads();

        // softmax per head: warp 0 -> head 0, warp 1 -> head 1
        {
            int w = tid >> 5, lane = tid & 31;
            if (w < 2) {
                float m = -1e30f;
                for (int j = lane; j < n; j += 32) m = fmaxf(m, s.sc[w * 128 + j]);
#pragma unroll
                for (int o = 16; o; o >>= 1) m = fmaxf(m, __shfl_xor_sync(0xffffffffu, m, o));
                float ssum = 0.f;
                for (int j = lane; j < n; j += 32) {
                    float e = expf(s.sc[w * 128 + j] - m);
                    s.sc[w * 128 + j] = e;
                    ssum += e;
                }
#pragma unroll
                for (int o = 16; o; o >>= 1) ssum += __shfl_xor_sync(0xffffffffu, ssum, o);
                if (lane == 0) s.inv2[w] = 1.f / ssum;
            }
        }
        __syncthreads();

        // sa[o] = sum_j p[h][j] * v[j][o]   (split-4 over j within warp)
        {
            int o = tid >> 2, sgi = tid & 3;
            int h = o >> 5;
            float acc = 0.f;
            for (int j = sgi; j < n; j += 4) acc += s.sc[h * 128 + j] * s.vc[j * 65 + o];
            acc += __shfl_xor_sync(0xffffffffu, acc, 1);
            acc += __shfl_xor_sync(0xffffffffu, acc, 2);
            if (sgi == 0) s.sa[o] = acc * s.inv2[h];
        }
        __syncthreads();

        // out proj + residual  ->  h1 pre-LN
        {
            int o = tid >> 2, sgi = tid & 3;
            float acc = 0.f;
#pragma unroll
            for (int j = sgi; j < 64; j += 4) acc += s.sa[j] * s.WoT[j * 65 + o];
            acc += __shfl_xor_sync(0xffffffffu, acc, 1);
            acc += __shfl_xor_sync(0xffffffffu, acc, 2);
            if (sgi == 0) s.h1[o] = s.xq[o] + acc + s.bo[o];
        }
        ln64_inplace(s.h1, s.g1, s.be1, tid, s.red);

        // persist h1 (kernel 3 computes the real output using cross[t])
        if (tid < 64) g_h1[t * 64 + tid] = s.h1[tid];
        if (t == TT - 1) break;   // last row: only h1 is needed

        // h2 = LN(h1 + cross_last)
        if (tid < 64) s.h2[tid] = s.h1[tid] + s.cl[tid];
        ln64_inplace(s.h2, s.g2, s.be2, tid, s.red);

        // FFN up:  u = relu(h2 @ W1^T + c1)  (128 outputs, split-2)
        {
            int o = tid >> 1, sgi = tid & 1;
            float acc = 0.f;
#pragma unroll
            for (int j = sgi; j < 64; j += 2) acc += s.h2[j] * s.W1T[j * 129 + o];
            acc += __shfl_xor_sync(0xffffffffu, acc, 1);
            if (sgi == 0) s.u[o] = fmaxf(acc + s.c1[o], 0.f);
        }
        __syncthreads();

        // FFN down + residual -> h3 pre-LN  (64 outputs, split-4 over 128)
        {
            int o = tid >> 2, sgi = tid & 3;
            float acc = 0.f;
#pragma unroll
            for (int j = sgi; j < 128; j += 4) acc += s.u[j] * s.W2T[j * 65 + o];
            acc += __shfl_xor_sync(0xffffffffu, acc, 1);
            acc += __shfl_xor_sync(0xffffffffu, acc, 2);
            if (sgi == 0) s.h3[o] = s.h2[o] + acc + s.c2[o];
        }
        ln64_inplace(s.h3, s.g3, s.be3, tid, s.red);

        // r = h3 @ Wr^T + br  (31 outputs, split-4)
        {
            int o = tid >> 2, sgi = tid & 3;
            if (o < 32) {
                float acc = 0.f;
#pragma unroll
                for (int j = sgi; j < 64; j += 4) acc += s.h3[j] * s.WrT[j * 33 + o];
                acc += __shfl_xor_sync(0xffffffffu, acc, 1);
                acc += __shfl_xor_sync(0xffffffffu, acc, 2);
                if (sgi == 0 && o < 31) s.r[o] = acc + s.br[o];
            }
        }
        __syncthreads();

        // emb[t+1] = r @ Wm^T + bm + style  (64 outputs, split-4 over 31)
        {
            int o = tid >> 2, sgi = tid & 3;
            float acc = 0.f;
            for (int j = sgi; j < 31; j += 4) acc += s.r[j] * s.WmT[j * 65 + o];
            acc += __shfl_xor_sync(0xffffffffu, acc, 1);
            acc += __shfl_xor_sync(0xffffffffu, acc, 2);
            if (sgi == 0) s.cur[o] = acc + s.bm[o] + s.style[o];
        }
        __syncthreads();
    }
}

// ---------------------------------------------------------------------------
// Kernel 3: per-row output tail (uses per-row cross[t], unlike the loop)
//   h2 = LN(h1[t] + cross[t]); h3 = LN(h2 + FFN(h2)); out = h3 @ Wr^T + br
// 120 blocks x 128 threads
// ---------------------------------------------------------------------------
__global__ void k3_out(const float* __restrict__ W1, const float* __restrict__ c1,
                       const float* __restrict__ W2, const float* __restrict__ c2,
                       const float* __restrict__ Wr, const float* __restrict__ br,
                       const float* __restrict__ g2, const float* __restrict__ be2,
                       const float* __restrict__ g3, const float* __restrict__ be3,
                       float* __restrict__ out) {
    int t = blockIdx.x, tid = threadIdx.x;
    __shared__ float h2[64], u[128], h3[64], red[2];

    if (tid < 64) h2[tid] = g_h1[t * 64 + tid] + g_cross[t * 64 + tid];
    ln64_inplace(h2, g2, be2, tid, red);

    float acc = c1[tid];
#pragma unroll 8
    for (int j = 0; j < 64; j++) acc += h2[j] * W1[tid * 64 + j];
    u[tid] = fmaxf(acc, 0.f);
    __syncthreads();

    if (tid < 64) {
        float a2 = c2[tid];
#pragma unroll 8
        for (int j = 0; j < 128; j++) a2 += u[j] * W2[tid * 128 + j];
        h3[tid] = h2[tid] + a2;
    }
    ln64_inplace(h3, g3, be3, tid, red);

    if (tid < 31) {
        float a3 = br[tid];
#pragma unroll 8
        for (int j = 0; j < 64; j++) a3 += h3[j] * Wr[tid * 64 + j];
        out[t * 31 + tid] = a3;
    }
}

// ---------------------------------------------------------------------------
extern "C" void kernel_launch(void* const* d_in, const int* in_sizes, int n_in,
                              void* d_out, int out_size) {
    const float* audio   = (const float*)d_in[0];
    const float* W_audio = (const float*)d_in[1];
    const float* b_audio = (const float*)d_in[2];
    const float* obj_W   = (const float*)d_in[3];
    const float* Wq = (const float*)d_in[4];  const float* bq = (const float*)d_in[5];
    const float* Wk = (const float*)d_in[6];  const float* bk = (const float*)d_in[7];
    const float* Wv = (const float*)d_in[8];  const float* bv = (const float*)d_in[9];
    const float* Wo = (const float*)d_in[10]; const float* bo = (const float*)d_in[11];
    const float* Wv2 = (const float*)d_in[12]; const float* bv2 = (const float*)d_in[13];
    const float* Wo2 = (const float*)d_in[14]; const float* bo2 = (const float*)d_in[15];
    const float* g1 = (const float*)d_in[16]; const float* be1 = (const float*)d_in[17];
    const float* g2 = (const float*)d_in[18]; const float* be2 = (const float*)d_in[19];
    const float* g3 = (const float*)d_in[20]; const float* be3 = (const float*)d_in[21];
    const float* W1 = (const float*)d_in[22]; const float* c1 = (const float*)d_in[23];
    const float* W2 = (const float*)d_in[24]; const float* c2 = (const float*)d_in[25];
    const float* Wr = (const float*)d_in[26]; const float* br = (const float*)d_in[27];
    const float* Wm = (const float*)d_in[28]; const float* bm = (const float*)d_in[29];
    float* out = (float*)d_out;

    cudaFuncSetAttribute(k2_seq, cudaFuncAttributeMaxDynamicSharedMemorySize,
                         (int)sizeof(S2));

    k1_mem_cross<<<TT, 256>>>(audio, W_audio, b_audio, Wv2, bv2, Wo2, bo2);
    k2_seq<<<1, 256, sizeof(S2)>>>(Wq, bq, Wk, bk, Wv, bv, Wo, bo,
                                   g1, be1, g2, be2, g3, be3,
                                   W1, c1, W2, c2, Wr, br, Wm, bm, obj_W);
    k3_out<<<TT, 128>>>(W1, c1, W2, c2, Wr, br, g2, be2, g3, be3, out);
}

// round 7
// speedup vs baseline: 1.0017x; 1.0003x over previous
#include <cuda_runtime.h>
#include <cmath>

#define TT   120
#define DD   64
#define DHH  32
#define NHH  2
#define DFF_ 128
#define DOUT_ 31
#define SCALE_ 0.17677669529663687f   // 1/sqrt(32)

// scratch (device globals: no allocation allowed)
__device__ float g_cross[TT * DD];
__device__ float g_h1[TT * DD];

// ---------------------------------------------------------------------------
// LayerNorm over 64 smem values, in place. All threads of block must call.
// ---------------------------------------------------------------------------
__device__ __forceinline__ void ln64_inplace(float* x, const float* g,
                                             const float* b, int tid,
                                             float* red) {
    __syncthreads();
    if (tid < 32) {
        float a = x[tid], c = x[tid + 32];
        float s = a + c, q = a * a + c * c;
#pragma unroll
        for (int o = 16; o; o >>= 1) {
            s += __shfl_xor_sync(0xffffffffu, s, o);
            q += __shfl_xor_sync(0xffffffffu, q, o);
        }
        if (tid == 0) {
            float m = s * (1.f / 64.f);
            red[0] = m;
            red[1] = rsqrtf(q * (1.f / 64.f) - m * m + 1e-5f);
        }
    }
    __syncthreads();
    if (tid < 64) x[tid] = (x[tid] - red[0]) * red[1] * g[tid] + b[tid];
    __syncthreads();
}

// ---------------------------------------------------------------------------
// Kernel 1: per-row  mem_t = audio[t] @ W_audio^T + b_audio  (64 x 1024 dot)
//           cross_t = (mem_t @ Wv2^T + bv2) @ Wo2^T + bo2
// 120 blocks x 256 threads (4 threads per output, shuffle reduce)
// ---------------------------------------------------------------------------
__global__ void k1_mem_cross(const float* __restrict__ audio,
                             const float* __restrict__ W_audio,
                             const float* __restrict__ b_audio,
                             const float* __restrict__ Wv2,
                             const float* __restrict__ bv2,
                             const float* __restrict__ Wo2,
                             const float* __restrict__ bo2) {
    int t = blockIdx.x;
    int tid = threadIdx.x;
    int o = tid >> 2, sgi = tid & 3;
    __shared__ float memv[64], tmp[64];

    const float4* a = (const float4*)(audio + t * 1024);
    const float4* w = (const float4*)(W_audio + o * 1024);
    float acc = 0.f;
    int base = sgi * 64;
#pragma unroll 8
    for (int j = 0; j < 64; j++) {
        float4 av = a[base + j], wv = w[base + j];
        acc += av.x * wv.x + av.y * wv.y + av.z * wv.z + av.w * wv.w;
    }
    acc += __shfl_xor_sync(0xffffffffu, acc, 1);
    acc += __shfl_xor_sync(0xffffffffu, acc, 2);
    if (sgi == 0) memv[o] = acc + b_audio[o];
    __syncthreads();

    float a2 = 0.f;
#pragma unroll
    for (int j = sgi; j < 64; j += 4) a2 += memv[j] * Wv2[o * 64 + j];
    a2 += __shfl_xor_sync(0xffffffffu, a2, 1);
    a2 += __shfl_xor_sync(0xffffffffu, a2, 2);
    if (sgi == 0) tmp[o] = a2 + bv2[o];
    __syncthreads();

    float a3 = 0.f;
#pragma unroll
    for (int j = sgi; j < 64; j += 4) a3 += tmp[j] * Wo2[o * 64 + j];
    a3 += __shfl_xor_sync(0xffffffffu, a3, 1);
    a3 += __shfl_xor_sync(0xffffffffu, a3, 2);
    if (sgi == 0) g_cross[t * 64 + o] = a3 + bo2[o];
}

// ---------------------------------------------------------------------------
// Kernel 2: sequential 120-step recurrence. ONE block, 256 threads.
// All weights (transposed, padded rows to kill bank conflicts) + K/V caches
// live in shared memory. h1[t] is saved to global for kernel 3.
// ---------------------------------------------------------------------------
struct S2 {
    float WqT[64 * 65];
    float WkT[64 * 65];
    float WvT[64 * 65];
    float WoT[64 * 65];
    float W1T[64 * 129];   // [in j<64][out i<128]
    float W2T[128 * 65];   // [in j<128][out i<64]
    float WrT[64 * 33];    // [in j<64][out i<31]
    float WmT[31 * 65];    // [in j<31][out i<64]
    float kcT[64 * 128];   // [dim][time]  (time padded to 128)
    float vc[120 * 65];    // [time][dim]  (dim padded to 65)
    float pe[10 * 64];
    float bq[64], bk[64], bv[64], bo[64];
    float c1[128], c2[64];
    float br[32], bm[64];
    float g1[64], be1[64], g2[64], be2[64], g3[64], be3[64];
    float cl[64], style[64];
    float cur[64], xq[64], q[64];
    float sc[2 * 128];
    float sa[64], h1[64], h2[64], u[128], h3[64], r[32];
    float red[2];
    float inv2[2];
};

__global__ void __launch_bounds__(256, 1)
k2_seq(const float* __restrict__ Wq, const float* __restrict__ bq,
       const float* __restrict__ Wk, const float* __restrict__ bk,
       const float* __restrict__ Wv, const float* __restrict__ bv,
       const float* __restrict__ Wo, const float* __restrict__ bo,
       const float* __restrict__ g1, const float* __restrict__ be1,
       const float* __restrict__ g2, const float* __restrict__ be2,
       const float* __restrict__ g3, const float* __restrict__ be3,
       const float* __restrict__ W1, const float* __restrict__ c1,
       const float* __restrict__ W2, const float* __restrict__ c2,
       const float* __restrict__ Wr, const float* __restrict__ br,
       const float* __restrict__ Wm, const float* __restrict__ bm,
       const float* __restrict__ obj_W) {
    extern __shared__ char raw[];
    S2& s = *reinterpret_cast<S2*>(raw);
    int tid = threadIdx.x;

    // ---- load weights (transposed) ----
    for (int idx = tid; idx < 4096; idx += 256) {
        int i = idx >> 6, j = idx & 63;
        s.WqT[j * 65 + i] = Wq[idx];
        s.WkT[j * 65 + i] = Wk[idx];
        s.WvT[j * 65 + i] = Wv[idx];
        s.WoT[j * 65 + i] = Wo[idx];
    }
    for (int idx = tid; idx < 8192; idx += 256) {       // W1 is (128,64)
        int i = idx >> 6, j = idx & 63;
        s.W1T[j * 129 + i] = W1[idx];
    }
    for (int idx = tid; idx < 8192; idx += 256) {       // W2 is (64,128)
        int i = idx >> 7, j = idx & 127;
        s.W2T[j * 65 + i] = W2[idx];
    }
    for (int idx = tid; idx < 31 * 64; idx += 256) {    // Wr is (31,64)
        int i = idx >> 6, j = idx & 63;
        s.WrT[j * 33 + i] = Wr[idx];
    }
    for (int idx = tid; idx < 64 * 31; idx += 256) {    // Wm is (64,31)
        int i = idx / 31, j = idx % 31;
        s.WmT[j * 65 + i] = Wm[idx];
    }
    if (tid < 64) {
        s.bq[tid] = bq[tid]; s.bk[tid] = bk[tid];
        s.bv[tid] = bv[tid]; s.bo[tid] = bo[tid];
        s.c2[tid] = c2[tid]; s.bm[tid] = bm[tid];
        s.g1[tid] = g1[tid]; s.be1[tid] = be1[tid];
        s.g2[tid] = g2[tid]; s.be2[tid] = be2[tid];
        s.g3[tid] = g3[tid]; s.be3[tid] = be3[tid];
        s.cl[tid] = g_cross[(TT - 1) * 64 + tid];
        float st = obj_W[tid * 5];          // obj_W[:,0], shape (64,5)
        s.style[tid] = st;
        s.cur[tid] = st;                    // emb[0] = style
    }
    if (tid < 128) s.c1[tid] = c1[tid];
    if (tid < 31) s.br[tid] = br[tid];
    // positional encoding (period 10, interleaved sin/cos)
    for (int idx = tid; idx < 640; idx += 256) {
        int p = idx >> 6, d = idx & 63;
        int i = d >> 1;
        float div = expf(-(float)(2 * i) * (9.210340371976184f / 64.f));
        float arg = (float)p * div;
        s.pe[idx] = (d & 1) ? cosf(arg) : sinf(arg);
    }
    __syncthreads();

    const float slopes[2] = {0.0625f, 0.00390625f};

    for (int t = 0; t < TT; t++) {
        // xq = emb[t] + pe[t % 10]
        if (tid < 64) s.xq[tid] = s.cur[tid] + s.pe[(t % 10) * 64 + tid];
        __syncthreads();

        // q / k_t / v_t  (192 outputs, one thread each, 64-term dot)
        if (tid < 192) {
            int which = tid >> 6, i = tid & 63;
            const float* WT = (which == 0) ? s.WqT : (which == 1) ? s.WkT : s.WvT;
            float acc = 0.f;
#pragma unroll
            for (int j = 0; j < 64; j++) acc += s.xq[j] * WT[j * 65 + i];
            if (which == 0)      s.q[i] = acc + s.bq[i];
            else if (which == 1) s.kcT[i * 128 + t] = acc + s.bk[i];
            else                 s.vc[t * 65 + i] = acc + s.bv[i];
        }
        __syncthreads();

        // attention scores: s[h][j] = (q_h . k_j,h)*SCALE - slope_h*((t-j)/10)
        int n = t + 1;
        if (tid < 2 * n) {
            int h = (tid >= n) ? 1 : 0;
            int j = tid - h * n;
            float acc = 0.f;
#pragma unroll
            for (int d = 0; d < 32; d++)
                acc += s.q[h * 32 + d] * s.kcT[(h * 32 + d) * 128 + j];
            s.sc[h * 128 + j] = acc * SCALE_ - slopes[h] * (float)((t - j) / 10);
        }
        __syncthreads();

        // softmax per head: warp 0 -> head 0, warp 1 -> head 1
        {
            int w = tid >> 5, lane = tid & 31;
            if (w < 2) {
                float m = -1e30f;
                for (int j = lane; j < n; j += 32) m = fmaxf(m, s.sc[w * 128 + j]);
#pragma unroll
                for (int o = 16; o; o >>= 1) m = fmaxf(m, __shfl_xor_sync(0xffffffffu, m, o));
                float ssum = 0.f;
                for (int j = lane; j < n; j += 32) {
                    float e = expf(s.sc[w * 128 + j] - m);
                    s.sc[w * 128 + j] = e;
                    ssum += e;
                }
#pragma unroll
                for (int o = 16; o; o >>= 1) ssum += __shfl_xor_sync(0xffffffffu, ssum, o);
                if (lane == 0) s.inv2[w] = 1.f / ssum;
            }
        }
        __syncthreads();

        // sa[o] = sum_j p[h][j] * v[j][o]   (split-4 over j within warp)
        {
            int o = tid >> 2, sgi = tid & 3;
            int h = o >> 5;
            float acc = 0.f;
            for (int j = sgi; j < n; j += 4) acc += s.sc[h * 128 + j] * s.vc[j * 65 + o];
            acc += __shfl_xor_sync(0xffffffffu, acc, 1);
            acc += __shfl_xor_sync(0xffffffffu, acc, 2);
            if (sgi == 0) s.sa[o] = acc * s.inv2[h];
        }
        __syncthreads();

        // out proj + residual  ->  h1 pre-LN
        {
            int o = tid >> 2, sgi = tid & 3;
            float acc = 0.f;
#pragma unroll
            for (int j = sgi; j < 64; j += 4) acc += s.sa[j] * s.WoT[j * 65 + o];
            acc += __shfl_xor_sync(0xffffffffu, acc, 1);
            acc += __shfl_xor_sync(0xffffffffu, acc, 2);
            if (sgi == 0) s.h1[o] = s.xq[o] + acc + s.bo[o];
        }
        ln64_inplace(s.h1, s.g1, s.be1, tid, s.red);

        // persist h1 (kernel 3 computes the real output using cross[t])
        if (tid < 64) g_h1[t * 64 + tid] = s.h1[tid];
        if (t == TT - 1) break;   // last row: only h1 is needed

        // h2 = LN(h1 + cross_last)
        if (tid < 64) s.h2[tid] = s.h1[tid] + s.cl[tid];
        ln64_inplace(s.h2, s.g2, s.be2, tid, s.red);

        // FFN up:  u = relu(h2 @ W1^T + c1)  (128 outputs, split-2)
        {
            int o = tid >> 1, sgi = tid & 1;
            float acc = 0.f;
#pragma unroll
            for (int j = sgi; j < 64; j += 2) acc += s.h2[j] * s.W1T[j * 129 + o];
            acc += __shfl_xor_sync(0xffffffffu, acc, 1);
            if (sgi == 0) s.u[o] = fmaxf(acc + s.c1[o], 0.f);
        }
        __syncthreads();

        // FFN down + residual -> h3 pre-LN  (64 outputs, split-4 over 128)
        {
            int o = tid >> 2, sgi = tid & 3;
            float acc = 0.f;
#pragma unroll
            for (int j = sgi; j < 128; j += 4) acc += s.u[j] * s.W2T[j * 65 + o];
            acc += __shfl_xor_sync(0xffffffffu, acc, 1);
            acc += __shfl_xor_sync(0xffffffffu, acc, 2);
            if (sgi == 0) s.h3[o] = s.h2[o] + acc + s.c2[o];
        }
        ln64_inplace(s.h3, s.g3, s.be3, tid, s.red);

        // r = h3 @ Wr^T + br  (31 outputs, split-4)
        {
            int o = tid >> 2, sgi = tid & 3;
            if (o < 32) {
                float acc = 0.f;
#pragma unroll
                for (int j = sgi; j < 64; j += 4) acc += s.h3[j] * s.WrT[j * 33 + o];
                acc += __shfl_xor_sync(0xffffffffu, acc, 1);
                acc += __shfl_xor_sync(0xffffffffu, acc, 2);
                if (sgi == 0 && o < 31) s.r[o] = acc + s.br[o];
            }
        }
        __syncthreads();

        // emb[t+1] = r @ Wm^T + bm + style  (64 outputs, split-4 over 31)
        {
            int o = tid >> 2, sgi = tid & 3;
            float acc = 0.f;
            for (int j = sgi; j < 31; j += 4) acc += s.r[j] * s.WmT[j * 65 + o];
            acc += __shfl_xor_sync(0xffffffffu, acc, 1);
            acc += __shfl_xor_sync(0xffffffffu, acc, 2);
            if (sgi == 0) s.cur[o] = acc + s.bm[o] + s.style[o];
        }
        __syncthreads();
    }
}

// ---------------------------------------------------------------------------
// Kernel 3: per-row output tail (uses per-row cross[t], unlike the loop)
//   h2 = LN(h1[t] + cross[t]); h3 = LN(h2 + FFN(h2)); out = h3 @ Wr^T + br
// 120 blocks x 128 threads
// ---------------------------------------------------------------------------
__global__ void k3_out(const float* __restrict__ W1, const float* __restrict__ c1,
                       const float* __restrict__ W2, const float* __restrict__ c2,
                       const float* __restrict__ Wr, const float* __restrict__ br,
                       const float* __restrict__ g2, const float* __restrict__ be2,
                       const float* __restrict__ g3, const float* __restrict__ be3,
                       float* __restrict__ out) {
    int t = blockIdx.x, tid = threadIdx.x;
    __shared__ float h2[64], u[128], h3[64], red[2];

    if (tid < 64) h2[tid] = g_h1[t * 64 + tid] + g_cross[t * 64 + tid];
    ln64_inplace(h2, g2, be2, tid, red);

    float acc = c1[tid];
#pragma unroll 8
    for (int j = 0; j < 64; j++) acc += h2[j] * W1[tid * 64 + j];
    u[tid] = fmaxf(acc, 0.f);
    __syncthreads();

    if (tid < 64) {
        float a2 = c2[tid];
#pragma unroll 8
        for (int j = 0; j < 128; j++) a2 += u[j] * W2[tid * 128 + j];
        h3[tid] = h2[tid] + a2;
    }
    ln64_inplace(h3, g3, be3, tid, red);

    if (tid < 31) {
        float a3 = br[tid];
#pragma unroll 8
        for (int j = 0; j < 64; j++) a3 += h3[j] * Wr[tid * 64 + j];
        out[t * 31 + tid] = a3;
    }
}

// ---------------------------------------------------------------------------
extern "C" void kernel_launch(void* const* d_in, const int* in_sizes, int n_in,
                              void* d_out, int out_size) {
    const float* audio   = (const float*)d_in[0];
    const float* W_audio = (const float*)d_in[1];
    const float* b_audio = (const float*)d_in[2];
    const float* obj_W   = (const float*)d_in[3];
    const float* Wq = (const float*)d_in[4];  const float* bq = (const float*)d_in[5];
    const float* Wk = (const float*)d_in[6];  const float* bk = (const float*)d_in[7];
    const float* Wv = (const float*)d_in[8];  const float* bv = (const float*)d_in[9];
    const float* Wo = (const float*)d_in[10]; const float* bo = (const float*)d_in[11];
    const float* Wv2 = (const float*)d_in[12]; const float* bv2 = (const float*)d_in[13];
    const float* Wo2 = (const float*)d_in[14]; const float* bo2 = (const float*)d_in[15];
    const float* g1 = (const float*)d_in[16]; const float* be1 = (const float*)d_in[17];
    const float* g2 = (const float*)d_in[18]; const float* be2 = (const float*)d_in[19];
    const float* g3 = (const float*)d_in[20]; const float* be3 = (const float*)d_in[21];
    const float* W1 = (const float*)d_in[22]; const float* c1 = (const float*)d_in[23];
    const float* W2 = (const float*)d_in[24]; const float* c2 = (const float*)d_in[25];
    const float* Wr = (const float*)d_in[26]; const float* br = (const float*)d_in[27];
    const float* Wm = (const float*)d_in[28]; const float* bm = (const float*)d_in[29];
    float* out = (float*)d_out;

    cudaFuncSetAttribute(k2_seq, cudaFuncAttributeMaxDynamicSharedMemorySize,
                         (int)sizeof(S2));

    k1_mem_cross<<<TT, 256>>>(audio, W_audio, b_audio, Wv2, bv2, Wo2, bo2);
    k2_seq<<<1, 256, sizeof(S2)>>>(Wq, bq, Wk, bk, Wv, bv, Wo, bo,
                                   g1, be1, g2, be2, g3, be3,
                                   W1, c1, W2, c2, Wr, br, Wm, bm, obj_W);
    k3_out<<<TT, 128>>>(W1, c1, W2, c2, Wr, br, g2, be2, g3, be3, out);
}

// round 8
// speedup vs baseline: 1.0025x; 1.0008x over previous
#include <cuda_runtime.h>
#include <cmath>

#define TT   120
#define DD   64
#define DHH  32
#define NHH  2
#define DFF_ 128
#define DOUT_ 31
#define SCALE_ 0.17677669529663687f   // 1/sqrt(32)

// scratch (device globals: no allocation allowed)
__device__ float g_cross[TT * DD];
__device__ float g_h1[TT * DD];

// ---------------------------------------------------------------------------
// LayerNorm over 64 smem values, in place. All threads of block must call.
// ---------------------------------------------------------------------------
__device__ __forceinline__ void ln64_inplace(float* x, const float* g,
                                             const float* b, int tid,
                                             float* red) {
    __syncthreads();
    if (tid < 32) {
        float a = x[tid], c = x[tid + 32];
        float s = a + c, q = a * a + c * c;
#pragma unroll
        for (int o = 16; o; o >>= 1) {
            s += __shfl_xor_sync(0xffffffffu, s, o);
            q += __shfl_xor_sync(0xffffffffu, q, o);
        }
        if (tid == 0) {
            float m = s * (1.f / 64.f);
            red[0] = m;
            red[1] = rsqrtf(q * (1.f / 64.f) - m * m + 1e-5f);
        }
    }
    __syncthreads();
    if (tid < 64) x[tid] = (x[tid] - red[0]) * red[1] * g[tid] + b[tid];
    __syncthreads();
}

// ---------------------------------------------------------------------------
// Kernel 1: per-row  mem_t = audio[t] @ W_audio^T + b_audio  (64 x 1024 dot)
//           cross_t = (mem_t @ Wv2^T + bv2) @ Wo2^T + bo2
// 120 blocks x 256 threads (4 threads per output, shuffle reduce)
// ---------------------------------------------------------------------------
__global__ void k1_mem_cross(const float* __restrict__ audio,
                             const float* __restrict__ W_audio,
                             const float* __restrict__ b_audio,
                             const float* __restrict__ Wv2,
                             const float* __restrict__ bv2,
                             const float* __restrict__ Wo2,
                             const float* __restrict__ bo2) {
    int t = blockIdx.x;
    int tid = threadIdx.x;
    int o = tid >> 2, sgi = tid & 3;
    __shared__ float memv[64], tmp[64];

    const float4* a = (const float4*)(audio + t * 1024);
    const float4* w = (const float4*)(W_audio + o * 1024);
    float acc = 0.f;
    int base = sgi * 64;
#pragma unroll 8
    for (int j = 0; j < 64; j++) {
        float4 av = a[base + j], wv = w[base + j];
        acc += av.x * wv.x + av.y * wv.y + av.z * wv.z + av.w * wv.w;
    }
    acc += __shfl_xor_sync(0xffffffffu, acc, 1);
    acc += __shfl_xor_sync(0xffffffffu, acc, 2);
    if (sgi == 0) memv[o] = acc + b_audio[o];
    __syncthreads();

    float a2 = 0.f;
#pragma unroll
    for (int j = sgi; j < 64; j += 4) a2 += memv[j] * Wv2[o * 64 + j];
    a2 += __shfl_xor_sync(0xffffffffu, a2, 1);
    a2 += __shfl_xor_sync(0xffffffffu, a2, 2);
    if (sgi == 0) tmp[o] = a2 + bv2[o];
    __syncthreads();

    float a3 = 0.f;
#pragma unroll
    for (int j = sgi; j < 64; j += 4) a3 += tmp[j] * Wo2[o * 64 + j];
    a3 += __shfl_xor_sync(0xffffffffu, a3, 1);
    a3 += __shfl_xor_sync(0xffffffffu, a3, 2);
    if (sgi == 0) g_cross[t * 64 + o] = a3 + bo2[o];
}

// ---------------------------------------------------------------------------
// Kernel 2: sequential 120-step recurrence. ONE block, 256 threads.
// All weights (transposed, padded rows to kill bank conflicts) + K/V caches
// live in shared memory. h1[t] is saved to global for kernel 3.
// ---------------------------------------------------------------------------
struct S2 {
    float WqT[64 * 65];
    float WkT[64 * 65];
    float WvT[64 * 65];
    float WoT[64 * 65];
    float W1T[64 * 129];   // [in j<64][out i<128]
    float W2T[128 * 65];   // [in j<128][out i<64]
    float WrT[64 * 33];    // [in j<64][out i<31]
    float WmT[31 * 65];    // [in j<31][out i<64]
    float kcT[64 * 128];   // [dim][time]  (time padded to 128)
    float vc[120 * 65];    // [time][dim]  (dim padded to 65)
    float pe[10 * 64];
    float bq[64], bk[64], bv[64], bo[64];
    float c1[128], c2[64];
    float br[32], bm[64];
    float g1[64], be1[64], g2[64], be2[64], g3[64], be3[64];
    float cl[64], style[64];
    float cur[64], xq[64], q[64];
    float sc[2 * 128];
    float sa[64], h1[64], h2[64], u[128], h3[64], r[32];
    float red[2];
    float inv2[2];
};

__global__ void __launch_bounds__(256, 1)
k2_seq(const float* __restrict__ Wq, const float* __restrict__ bq,
       const float* __restrict__ Wk, const float* __restrict__ bk,
       const float* __restrict__ Wv, const float* __restrict__ bv,
       const float* __restrict__ Wo, const float* __restrict__ bo,
       const float* __restrict__ g1, const float* __restrict__ be1,
       const float* __restrict__ g2, const float* __restrict__ be2,
       const float* __restrict__ g3, const float* __restrict__ be3,
       const float* __restrict__ W1, const float* __restrict__ c1,
       const float* __restrict__ W2, const float* __restrict__ c2,
       const float* __restrict__ Wr, const float* __restrict__ br,
       const float* __restrict__ Wm, const float* __restrict__ bm,
       const float* __restrict__ obj_W) {
    extern __shared__ char raw[];
    S2& s = *reinterpret_cast<S2*>(raw);
    int tid = threadIdx.x;

    // ---- load weights (transposed) ----
    for (int idx = tid; idx < 4096; idx += 256) {
        int i = idx >> 6, j = idx & 63;
        s.WqT[j * 65 + i] = Wq[idx];
        s.WkT[j * 65 + i] = Wk[idx];
        s.WvT[j * 65 + i] = Wv[idx];
        s.WoT[j * 65 + i] = Wo[idx];
    }
    for (int idx = tid; idx < 8192; idx += 256) {       // W1 is (128,64)
        int i = idx >> 6, j = idx & 63;
        s.W1T[j * 129 + i] = W1[idx];
    }
    for (int idx = tid; idx < 8192; idx += 256) {       // W2 is (64,128)
        int i = idx >> 7, j = idx & 127;
        s.W2T[j * 65 + i] = W2[idx];
    }
    for (int idx = tid; idx < 31 * 64; idx += 256) {    // Wr is (31,64)
        int i = idx >> 6, j = idx & 63;
        s.WrT[j * 33 + i] = Wr[idx];
    }
    for (int idx = tid; idx < 64 * 31; idx += 256) {    // Wm is (64,31)
        int i = idx / 31, j = idx % 31;
        s.WmT[j * 65 + i] = Wm[idx];
    }
    if (tid < 64) {
        s.bq[tid] = bq[tid]; s.bk[tid] = bk[tid];
        s.bv[tid] = bv[tid]; s.bo[tid] = bo[tid];
        s.c2[tid] = c2[tid]; s.bm[tid] = bm[tid];
        s.g1[tid] = g1[tid]; s.be1[tid] = be1[tid];
        s.g2[tid] = g2[tid]; s.be2[tid] = be2[tid];
        s.g3[tid] = g3[tid]; s.be3[tid] = be3[tid];
        s.cl[tid] = g_cross[(TT - 1) * 64 + tid];
        float st = obj_W[tid * 5];          // obj_W[:,0], shape (64,5)
        s.style[tid] = st;
        s.cur[tid] = st;                    // emb[0] = style
    }
    if (tid < 128) s.c1[tid] = c1[tid];
    if (tid < 31) s.br[tid] = br[tid];
    // positional encoding (period 10, interleaved sin/cos)
    for (int idx = tid; idx < 640; idx += 256) {
        int p = idx >> 6, d = idx & 63;
        int i = d >> 1;
        float div = expf(-(float)(2 * i) * (9.210340371976184f / 64.f));
        float arg = (float)p * div;
        s.pe[idx] = (d & 1) ? cosf(arg) : sinf(arg);
    }
    __syncthreads();

    const float slopes[2] = {0.0625f, 0.00390625f};

    for (int t = 0; t < TT; t++) {
        // xq = emb[t] + pe[t % 10]
        if (tid < 64) s.xq[tid] = s.cur[tid] + s.pe[(t % 10) * 64 + tid];
        __syncthreads();

        // q / k_t / v_t  (192 outputs, one thread each, 64-term dot)
        if (tid < 192) {
            int which = tid >> 6, i = tid & 63;
            const float* WT = (which == 0) ? s.WqT : (which == 1) ? s.WkT : s.WvT;
            float acc = 0.f;
#pragma unroll
            for (int j = 0; j < 64; j++) acc += s.xq[j] * WT[j * 65 + i];
            if (which == 0)      s.q[i] = acc + s.bq[i];
            else if (which == 1) s.kcT[i * 128 + t] = acc + s.bk[i];
            else                 s.vc[t * 65 + i] = acc + s.bv[i];
        }
        __syncthreads();

        // attention scores: s[h][j] = (q_h . k_j,h)*SCALE - slope_h*((t-j)/10)
        int n = t + 1;
        if (tid < 2 * n) {
            int h = (tid >= n) ? 1 : 0;
            int j = tid - h * n;
            float acc = 0.f;
#pragma unroll
            for (int d = 0; d < 32; d++)
                acc += s.q[h * 32 + d] * s.kcT[(h * 32 + d) * 128 + j];
            s.sc[h * 128 + j] = acc * SCALE_ - slopes[h] * (float)((t - j) / 10);
        }
        __syncthreads();

        // softmax per head: warp 0 -> head 0, warp 1 -> head 1
        {
            int w = tid >> 5, lane = tid & 31;
            if (w < 2) {
                float m = -1e30f;
                for (int j = lane; j < n; j += 32) m = fmaxf(m, s.sc[w * 128 + j]);
#pragma unroll
                for (int o = 16; o; o >>= 1) m = fmaxf(m, __shfl_xor_sync(0xffffffffu, m, o));
                float ssum = 0.f;
                for (int j = lane; j < n; j += 32) {
                    float e = expf(s.sc[w * 128 + j] - m);
                    s.sc[w * 128 + j] = e;
                    ssum += e;
                }
#pragma unroll
                for (int o = 16; o; o >>= 1) ssum += __shfl_xor_sync(0xffffffffu, ssum, o);
                if (lane == 0) s.inv2[w] = 1.f / ssum;
            }
        }
        __syncthreads();

        // sa[o] = sum_j p[h][j] * v[j][o]   (split-4 over j within warp)
        {
            int o = tid >> 2, sgi = tid & 3;
            int h = o >> 5;
            float acc = 0.f;
            for (int j = sgi; j < n; j += 4) acc += s.sc[h * 128 + j] * s.vc[j * 65 + o];
            acc += __shfl_xor_sync(0xffffffffu, acc, 1);
            acc += __shfl_xor_sync(0xffffffffu, acc, 2);
            if (sgi == 0) s.sa[o] = acc * s.inv2[h];
        }
        __syncthreads();

        // out proj + residual  ->  h1 pre-LN
        {
            int o = tid >> 2, sgi = tid & 3;
            float acc = 0.f;
#pragma unroll
            for (int j = sgi; j < 64; j += 4) acc += s.sa[j] * s.WoT[j * 65 + o];
            acc += __shfl_xor_sync(0xffffffffu, acc, 1);
            acc += __shfl_xor_sync(0xffffffffu, acc, 2);
            if (sgi == 0) s.h1[o] = s.xq[o] + acc + s.bo[o];
        }
        ln64_inplace(s.h1, s.g1, s.be1, tid, s.red);

        // persist h1 (kernel 3 computes the real output using cross[t])
        if (tid < 64) g_h1[t * 64 + tid] = s.h1[tid];
        if (t == TT - 1) break;   // last row: only h1 is needed

        // h2 = LN(h1 + cross_last)
        if (tid < 64) s.h2[tid] = s.h1[tid] + s.cl[tid];
        ln64_inplace(s.h2, s.g2, s.be2, tid, s.red);

        // FFN up:  u = relu(h2 @ W1^T + c1)  (128 outputs, split-2)
        {
            int o = tid >> 1, sgi = tid & 1;
            float acc = 0.f;
#pragma unroll
            for (int j = sgi; j < 64; j += 2) acc += s.h2[j] * s.W1T[j * 129 + o];
            acc += __shfl_xor_sync(0xffffffffu, acc, 1);
            if (sgi == 0) s.u[o] = fmaxf(acc + s.c1[o], 0.f);
        }
        __syncthreads();

        // FFN down + residual -> h3 pre-LN  (64 outputs, split-4 over 128)
        {
            int o = tid >> 2, sgi = tid & 3;
            float acc = 0.f;
#pragma unroll
            for (int j = sgi; j < 128; j += 4) acc += s.u[j] * s.W2T[j * 65 + o];
            acc += __shfl_xor_sync(0xffffffffu, acc, 1);
            acc += __shfl_xor_sync(0xffffffffu, acc, 2);
            if (sgi == 0) s.h3[o] = s.h2[o] + acc + s.c2[o];
        }
        ln64_inplace(s.h3, s.g3, s.be3, tid, s.red);

        // r = h3 @ Wr^T + br  (31 outputs, split-4)
        {
            int o = tid >> 2, sgi = tid & 3;
            if (o < 32) {
                float acc = 0.f;
#pragma unroll
                for (int j = sgi; j < 64; j += 4) acc += s.h3[j] * s.WrT[j * 33 + o];
                acc += __shfl_xor_sync(0xffffffffu, acc, 1);
                acc += __shfl_xor_sync(0xffffffffu, acc, 2);
                if (sgi == 0 && o < 31) s.r[o] = acc + s.br[o];
            }
        }
        __syncthreads();

        // emb[t+1] = r @ Wm^T + bm + style  (64 outputs, split-4 over 31)
        {
            int o = tid >> 2, sgi = tid & 3;
            float acc = 0.f;
            for (int j = sgi; j < 31; j += 4) acc += s.r[j] * s.WmT[j * 65 + o];
            acc += __shfl_xor_sync(0xffffffffu, acc, 1);
            acc += __shfl_xor_sync(0xffffffffu, acc, 2);
            if (sgi == 0) s.cur[o] = acc + s.bm[o] + s.style[o];
        }
        __syncthreads();
    }
}

// ---------------------------------------------------------------------------
// Kernel 3: per-row output tail (uses per-row cross[t], unlike the loop)
//   h2 = LN(h1[t] + cross[t]); h3 = LN(h2 + FFN(h2)); out = h3 @ Wr^T + br
// 120 blocks x 128 threads
// ---------------------------------------------------------------------------
__global__ void k3_out(const float* __restrict__ W1, const float* __restrict__ c1,
                       const float* __restrict__ W2, const float* __restrict__ c2,
                       const float* __restrict__ Wr, const float* __restrict__ br,
                       const float* __restrict__ g2, const float* __restrict__ be2,
                       const float* __restrict__ g3, const float* __restrict__ be3,
                       float* __restrict__ out) {
    int t = blockIdx.x, tid = threadIdx.x;
    __shared__ float h2[64], u[128], h3[64], red[2];

    if (tid < 64) h2[tid] = g_h1[t * 64 + tid] + g_cross[t * 64 + tid];
    ln64_inplace(h2, g2, be2, tid, red);

    float acc = c1[tid];
#pragma unroll 8
    for (int j = 0; j < 64; j++) acc += h2[j] * W1[tid * 64 + j];
    u[tid] = fmaxf(acc, 0.f);
    __syncthreads();

    if (tid < 64) {
        float a2 = c2[tid];
#pragma unroll 8
        for (int j = 0; j < 128; j++) a2 += u[j] * W2[tid * 128 + j];
        h3[tid] = h2[tid] + a2;
    }
    ln64_inplace(h3, g3, be3, tid, red);

    if (tid < 31) {
        float a3 = br[tid];
#pragma unroll 8
        for (int j = 0; j < 64; j++) a3 += h3[j] * Wr[tid * 64 + j];
        out[t * 31 + tid] = a3;
    }
}

// ---------------------------------------------------------------------------
extern "C" void kernel_launch(void* const* d_in, const int* in_sizes, int n_in,
                              void* d_out, int out_size) {
    const float* audio   = (const float*)d_in[0];
    const float* W_audio = (const float*)d_in[1];
    const float* b_audio = (const float*)d_in[2];
    const float* obj_W   = (const float*)d_in[3];
    const float* Wq = (const float*)d_in[4];  const float* bq = (const float*)d_in[5];
    const float* Wk = (const float*)d_in[6];  const float* bk = (const float*)d_in[7];
    const float* Wv = (const float*)d_in[8];  const float* bv = (const float*)d_in[9];
    const float* Wo = (const float*)d_in[10]; const float* bo = (const float*)d_in[11];
    const float* Wv2 = (const float*)d_in[12]; const float* bv2 = (const float*)d_in[13];
    const float* Wo2 = (const float*)d_in[14]; const float* bo2 = (const float*)d_in[15];
    const float* g1 = (const float*)d_in[16]; const float* be1 = (const float*)d_in[17];
    const float* g2 = (const float*)d_in[18]; const float* be2 = (const float*)d_in[19];
    const float* g3 = (const float*)d_in[20]; const float* be3 = (const float*)d_in[21];
    const float* W1 = (const float*)d_in[22]; const float* c1 = (const float*)d_in[23];
    const float* W2 = (const float*)d_in[24]; const float* c2 = (const float*)d_in[25];
    const float* Wr = (const float*)d_in[26]; const float* br = (const float*)d_in[27];
    const float* Wm = (const float*)d_in[28]; const float* bm = (const float*)d_in[29];
    float* out = (float*)d_out;

    cudaFuncSetAttribute(k2_seq, cudaFuncAttributeMaxDynamicSharedMemorySize,
                         (int)sizeof(S2));

    k1_mem_cross<<<TT, 256>>>(audio, W_audio, b_audio, Wv2, bv2, Wo2, bo2);
    k2_seq<<<1, 256, sizeof(S2)>>>(Wq, bq, Wk, bk, Wv, bv, Wo, bo,
                                   g1, be1, g2, be2, g3, be3,
                                   W1, c1, W2, c2, Wr, br, Wm, bm, obj_W);
    k3_out<<<TT, 128>>>(W1, c1, W2, c2, Wr, br, g2, be2, g3, be3, out);
}